// round 3
// baseline (speedup 1.0000x reference)
#include <cuda_runtime.h>
#include <math.h>
#include <stdint.h>

// Problem dims
#define BB 32
#define TT 256
#define CC 384
#define LL 6
#define NH 6
#define HD 64
#define VV 32000
#define MM (BB*TT)      // 8192
#define FF (4*CC)       // 1536

// Scratch (device globals; no allocations allowed)
__device__ float g_x[MM*CC];
__device__ float g_h[MM*CC];
__device__ float g_q[MM*CC];
__device__ float g_k[MM*CC];
__device__ float g_v[MM*CC];
__device__ float g_att[MM*CC];
__device__ float g_u[MM*FF];

// ---------------------------------------------------------------------------
// Helpers
// ---------------------------------------------------------------------------
__device__ __forceinline__ uint32_t f2tf(float f) {
    uint32_t u;
    asm("cvt.rna.tf32.f32 %0, %1;" : "=r"(u) : "f"(f));
    return u;
}

__device__ __forceinline__ void mma_tf32(float* c, const uint32_t* a, const uint32_t* b) {
    asm volatile(
        "mma.sync.aligned.m16n8k8.row.col.f32.tf32.tf32.f32 "
        "{%0,%1,%2,%3}, {%4,%5,%6,%7}, {%8,%9}, {%0,%1,%2,%3};"
        : "+f"(c[0]), "+f"(c[1]), "+f"(c[2]), "+f"(c[3])
        : "r"(a[0]), "r"(a[1]), "r"(a[2]), "r"(a[3]),
          "r"(b[0]), "r"(b[1]));
}

// ---------------------------------------------------------------------------
// Embedding
// ---------------------------------------------------------------------------
__global__ void embed_kernel(const int* __restrict__ idx,
                             const float* __restrict__ tok,
                             const float* __restrict__ pos,
                             float* __restrict__ X)
{
    int i = blockIdx.x * blockDim.x + threadIdx.x;
    if (i >= MM * (CC/4)) return;
    int row = i / (CC/4);
    int c4  = i % (CC/4);
    int t   = idx[row];
    int p   = row & (TT-1);
    float4 a = *(const float4*)(tok + (size_t)t*CC + c4*4);
    float4 e = *(const float4*)(pos + (size_t)p*CC + c4*4);
    a.x += e.x; a.y += e.y; a.z += e.z; a.w += e.w;
    *(float4*)(X + (size_t)row*CC + c4*4) = a;
}

// ---------------------------------------------------------------------------
// LayerNorm: one warp per row of 384
// ---------------------------------------------------------------------------
__global__ void ln_kernel(const float* __restrict__ X,
                          const float* __restrict__ g,
                          const float* __restrict__ b,
                          float* __restrict__ Y)
{
    int row  = blockIdx.x * 8 + (threadIdx.x >> 5);
    int lane = threadIdx.x & 31;
    if (row >= MM) return;
    const float* x = X + (size_t)row*CC;
    float v[12];
    float s = 0.f, ss = 0.f;
#pragma unroll
    for (int i = 0; i < 12; i++) {
        v[i] = x[lane + i*32];
        s  += v[i];
        ss += v[i]*v[i];
    }
#pragma unroll
    for (int o = 16; o; o >>= 1) {
        s  += __shfl_xor_sync(0xFFFFFFFFu, s,  o);
        ss += __shfl_xor_sync(0xFFFFFFFFu, ss, o);
    }
    float mean = s  * (1.0f/CC);
    float var  = ss * (1.0f/CC) - mean*mean;
    float inv  = rsqrtf(var + 1e-5f);
    float* y = Y + (size_t)row*CC;
#pragma unroll
    for (int i = 0; i < 12; i++) {
        int c = lane + i*32;
        y[c] = (v[i]-mean)*inv*g[c] + b[c];
    }
}

// ---------------------------------------------------------------------------
// Core TF32 GEMM device function: one 128x128 block tile at (bm, bn).
// BK=16, double-buffered smem, register prefetch, 256 threads, 8 warps
// each computing 64x32 via m16n8k8.
// ---------------------------------------------------------------------------
struct SmemGemm {
    uint32_t As[2][128][20];   // [stage][m][k] pad 20
    uint32_t Bs[2][16][136];   // [stage][k][n] pad 136
};

template<bool RELU, bool RES>
__device__ __forceinline__
void gemm_tile(SmemGemm* sm,
               const float* __restrict__ A, const float* __restrict__ B,
               const float* __restrict__ bias, const float* __restrict__ res,
               float* __restrict__ C, int M, int N, int K, int bm, int bn)
{
    const int tid  = threadIdx.x;
    const int lane = tid & 31;
    const int wid  = tid >> 5;
    const int wm = (wid & 1) * 64;
    const int wn = (wid >> 1) * 32;
    const int grp = lane >> 2;
    const int tg  = lane & 3;

    // load indices
    const int ar0 = tid >> 1;                // pattern for A: f = tid*2+p
    // A float4 f: r=f>>2, c4=(f&3)*4 ; B float4 f: r=f>>5, c4=(f&31)*4

    float acc[4][4][4];
#pragma unroll
    for (int mt = 0; mt < 4; mt++)
#pragma unroll
        for (int nt = 0; nt < 4; nt++)
#pragma unroll
            for (int e = 0; e < 4; e++) acc[mt][nt][e] = 0.f;

    float4 pa[2], pb[2];

    auto ldg = [&](int k0) {
#pragma unroll
        for (int p = 0; p < 2; p++) {
            int f  = tid*2 + p;
            int r  = f >> 2;
            int c4 = (f & 3) * 4;
            pa[p] = *(const float4*)(A + (size_t)(bm + r)*K + k0 + c4);
        }
#pragma unroll
        for (int p = 0; p < 2; p++) {
            int f  = tid*2 + p;
            int r  = f >> 5;
            int c4 = (f & 31) * 4;
            pb[p] = *(const float4*)(B + (size_t)(k0 + r)*N + bn + c4);
        }
    };
    auto sts = [&](int s) {
#pragma unroll
        for (int p = 0; p < 2; p++) {
            int f  = tid*2 + p;
            int r  = f >> 2;
            int c4 = (f & 3) * 4;
            uint4 u;
            u.x = f2tf(pa[p].x); u.y = f2tf(pa[p].y);
            u.z = f2tf(pa[p].z); u.w = f2tf(pa[p].w);
            *(uint4*)&sm->As[s][r][c4] = u;
        }
#pragma unroll
        for (int p = 0; p < 2; p++) {
            int f  = tid*2 + p;
            int r  = f >> 5;
            int c4 = (f & 31) * 4;
            uint4 u;
            u.x = f2tf(pb[p].x); u.y = f2tf(pb[p].y);
            u.z = f2tf(pb[p].z); u.w = f2tf(pb[p].w);
            *(uint4*)&sm->Bs[s][r][c4] = u;
        }
    };

    const int nIter = K >> 4;
    ldg(0);
    sts(0);
    __syncthreads();

    for (int it = 0; it < nIter; it++) {
        int cur = it & 1;
        if (it + 1 < nIter) ldg((it + 1) << 4);

#pragma unroll
        for (int kk = 0; kk < 16; kk += 8) {
            uint32_t af[4][4], bf[4][2];
#pragma unroll
            for (int mt = 0; mt < 4; mt++) {
                int r = wm + mt*16 + grp;
                af[mt][0] = sm->As[cur][r    ][kk + tg    ];
                af[mt][1] = sm->As[cur][r + 8][kk + tg    ];
                af[mt][2] = sm->As[cur][r    ][kk + tg + 4];
                af[mt][3] = sm->As[cur][r + 8][kk + tg + 4];
            }
#pragma unroll
            for (int nt = 0; nt < 4; nt++) {
                int c = wn + nt*8 + grp;
                bf[nt][0] = sm->Bs[cur][kk + tg    ][c];
                bf[nt][1] = sm->Bs[cur][kk + tg + 4][c];
            }
#pragma unroll
            for (int mt = 0; mt < 4; mt++)
#pragma unroll
                for (int nt = 0; nt < 4; nt++)
                    mma_tf32(acc[mt][nt], af[mt], bf[nt]);
        }

        if (it + 1 < nIter) {
            sts(cur ^ 1);
            __syncthreads();
        }
    }

    // Epilogue
#pragma unroll
    for (int mt = 0; mt < 4; mt++) {
        int r0 = bm + wm + mt*16 + grp;
        int r1 = r0 + 8;
#pragma unroll
        for (int nt = 0; nt < 4; nt++) {
            int c = bn + wn + nt*8 + tg*2;
            float o0x = acc[mt][nt][0], o0y = acc[mt][nt][1];
            float o1x = acc[mt][nt][2], o1y = acc[mt][nt][3];
            if (bias) {
                float bv0 = bias[c], bv1 = bias[c+1];
                o0x += bv0; o0y += bv1; o1x += bv0; o1y += bv1;
            }
            if (RES) {
                float2 ra = *(const float2*)(res + (size_t)r0*N + c);
                float2 rb = *(const float2*)(res + (size_t)r1*N + c);
                o0x += ra.x; o0y += ra.y; o1x += rb.x; o1y += rb.y;
            }
            if (RELU) {
                o0x = fmaxf(o0x, 0.f); o0y = fmaxf(o0y, 0.f);
                o1x = fmaxf(o1x, 0.f); o1y = fmaxf(o1y, 0.f);
            }
            float2 w0 = {o0x, o0y};
            float2 w1 = {o1x, o1y};
            *(float2*)(C + (size_t)r0*N + c) = w0;
            *(float2*)(C + (size_t)r1*N + c) = w1;
        }
    }
    (void)ar0;
}

template<bool RELU, bool RES>
__global__ __launch_bounds__(256, 2)
void tgemm(const float* __restrict__ A, const float* __restrict__ B,
           const float* __restrict__ bias, const float* __restrict__ res,
           float* __restrict__ C, int M, int N, int K)
{
    __shared__ SmemGemm sm;
    gemm_tile<RELU, RES>(&sm, A, B, bias, res, C, M, N, K,
                         blockIdx.y * 128, blockIdx.x * 128);
}

// Fused QKV: grid.x = 9 (3 matrices x 3 col-tiles of 128), grid.y = 64.
__global__ __launch_bounds__(256, 2)
void qkv_gemm(const float* __restrict__ A,
              const float* __restrict__ Wq, const float* __restrict__ Wk,
              const float* __restrict__ Wv,
              float* __restrict__ Q, float* __restrict__ Ko, float* __restrict__ V)
{
    __shared__ SmemGemm sm;
    int sel = blockIdx.x / 3;
    int bn  = (blockIdx.x % 3) * 128;
    const float* B = (sel == 0) ? Wq : (sel == 1) ? Wk : Wv;
    float*       C = (sel == 0) ? Q  : (sel == 1) ? Ko : V;
    gemm_tile<false, false>(&sm, A, B, nullptr, nullptr, C,
                            MM, CC, CC, blockIdx.y * 128, bn);
}

// ---------------------------------------------------------------------------
// Attention: 1 block per (batch, head), online softmax, causal.
// ---------------------------------------------------------------------------
#define KV_STRIDE 68
#define ATT_SMEM (2 * TT * KV_STRIDE * (int)sizeof(float))

__global__ __launch_bounds__(256, 1)
void attn_kernel(const float* __restrict__ Q, const float* __restrict__ K,
                 const float* __restrict__ V, float* __restrict__ O)
{
    extern __shared__ float sm[];
    float* Ks = sm;
    float* Vs = sm + TT*KV_STRIDE;

    const int bh = blockIdx.x;
    const int b  = bh / NH;
    const int h  = bh % NH;
    const float scale = 0.05103103630798288f;  // 1/sqrt(384)

    const float* kbase = K + (size_t)b*TT*CC + h*HD;
    const float* vbase = V + (size_t)b*TT*CC + h*HD;

    for (int i = threadIdx.x; i < TT*16; i += 256) {
        int t  = i >> 4;
        int d4 = (i & 15) * 4;
        *(float4*)(Ks + t*KV_STRIDE + d4) = *(const float4*)(kbase + (size_t)t*CC + d4);
        *(float4*)(Vs + t*KV_STRIDE + d4) = *(const float4*)(vbase + (size_t)t*CC + d4);
    }
    __syncthreads();

    const int t = threadIdx.x;
    const float* qrow = Q + (size_t)b*TT*CC + (size_t)t*CC + h*HD;
    float q[HD];
#pragma unroll
    for (int d4 = 0; d4 < 16; d4++) {
        float4 v4 = *(const float4*)(qrow + d4*4);
        q[d4*4+0]=v4.x; q[d4*4+1]=v4.y; q[d4*4+2]=v4.z; q[d4*4+3]=v4.w;
    }

    float m = -1e30f, l = 0.f;
    float acc[HD];
#pragma unroll
    for (int d = 0; d < HD; d++) acc[d] = 0.f;

    for (int s = 0; s <= t; s++) {
        const float* kr = Ks + s*KV_STRIDE;
        float dot = 0.f;
#pragma unroll
        for (int d4 = 0; d4 < 16; d4++) {
            float4 kv = *(const float4*)(kr + d4*4);
            dot += q[d4*4+0]*kv.x + q[d4*4+1]*kv.y + q[d4*4+2]*kv.z + q[d4*4+3]*kv.w;
        }
        dot *= scale;
        float mn   = fmaxf(m, dot);
        float corr = __expf(m - mn);
        float p    = __expf(dot - mn);
        l = l*corr + p;
        const float* vr = Vs + s*KV_STRIDE;
#pragma unroll
        for (int d4 = 0; d4 < 16; d4++) {
            float4 vv = *(const float4*)(vr + d4*4);
            acc[d4*4+0] = acc[d4*4+0]*corr + p*vv.x;
            acc[d4*4+1] = acc[d4*4+1]*corr + p*vv.y;
            acc[d4*4+2] = acc[d4*4+2]*corr + p*vv.z;
            acc[d4*4+3] = acc[d4*4+3]*corr + p*vv.w;
        }
        m = mn;
    }

    float inv = 1.f / l;
    float* orow = O + (size_t)b*TT*CC + (size_t)t*CC + h*HD;
#pragma unroll
    for (int d4 = 0; d4 < 16; d4++) {
        float4 o;
        o.x = acc[d4*4+0]*inv; o.y = acc[d4*4+1]*inv;
        o.z = acc[d4*4+2]*inv; o.w = acc[d4*4+3]*inv;
        *(float4*)(orow + d4*4) = o;
    }
}

// ---------------------------------------------------------------------------
// Host
// ---------------------------------------------------------------------------
static void gemm(const float* A, const float* B, const float* bias, const float* res,
                 float* C, int M, int N, int K, bool relu, bool hasRes)
{
    dim3 grid(N/128, M/128);
    if (relu)        tgemm<true,  false><<<grid, 256>>>(A, B, bias, res, C, M, N, K);
    else if (hasRes) tgemm<false, true ><<<grid, 256>>>(A, B, bias, res, C, M, N, K);
    else             tgemm<false, false><<<grid, 256>>>(A, B, bias, res, C, M, N, K);
}

extern "C" void kernel_launch(void* const* d_in, const int* in_sizes, int n_in,
                              void* d_out, int out_size)
{
    (void)in_sizes; (void)n_in; (void)out_size;

    const int*   idx     = (const int*)  d_in[0];
    const float* tok_emb = (const float*)d_in[1];
    const float* pos_emb = (const float*)d_in[2];
    const float* ln1_g   = (const float*)d_in[3];
    const float* ln1_b   = (const float*)d_in[4];
    const float* wq      = (const float*)d_in[5];
    const float* wk      = (const float*)d_in[6];
    const float* wv      = (const float*)d_in[7];
    const float* wo      = (const float*)d_in[8];
    const float* wo_b    = (const float*)d_in[9];
    const float* ln2_g   = (const float*)d_in[10];
    const float* ln2_b   = (const float*)d_in[11];
    const float* w1      = (const float*)d_in[12];
    const float* b1      = (const float*)d_in[13];
    const float* w2      = (const float*)d_in[14];
    const float* b2      = (const float*)d_in[15];
    const float* lnf_g   = (const float*)d_in[16];
    const float* lnf_b   = (const float*)d_in[17];
    const float* lm_w    = (const float*)d_in[18];
    const float* lm_b    = (const float*)d_in[19];
    float* out = (float*)d_out;

    float *x, *h, *q, *k, *v, *att, *u;
    cudaGetSymbolAddress((void**)&x,   g_x);
    cudaGetSymbolAddress((void**)&h,   g_h);
    cudaGetSymbolAddress((void**)&q,   g_q);
    cudaGetSymbolAddress((void**)&k,   g_k);
    cudaGetSymbolAddress((void**)&v,   g_v);
    cudaGetSymbolAddress((void**)&att, g_att);
    cudaGetSymbolAddress((void**)&u,   g_u);

    cudaFuncSetAttribute(attn_kernel, cudaFuncAttributeMaxDynamicSharedMemorySize, ATT_SMEM);

    {
        int total = MM * (CC/4);
        embed_kernel<<<(total + 255)/256, 256>>>(idx, tok_emb, pos_emb, x);
    }

    for (int L = 0; L < LL; L++) {
        const float* g1  = ln1_g + (size_t)L*CC;
        const float* bg1 = ln1_b + (size_t)L*CC;
        const float* Wq  = wq   + (size_t)L*CC*CC;
        const float* Wk  = wk   + (size_t)L*CC*CC;
        const float* Wv  = wv   + (size_t)L*CC*CC;
        const float* Wo  = wo   + (size_t)L*CC*CC;
        const float* Wob = wo_b + (size_t)L*CC;
        const float* g2  = ln2_g + (size_t)L*CC;
        const float* bg2 = ln2_b + (size_t)L*CC;
        const float* W1  = w1 + (size_t)L*CC*FF;
        const float* B1  = b1 + (size_t)L*FF;
        const float* W2  = w2 + (size_t)L*FF*CC;
        const float* B2  = b2 + (size_t)L*CC;

        ln_kernel<<<MM/8, 256>>>(x, g1, bg1, h);
        qkv_gemm<<<dim3(9, 64), 256>>>(h, Wq, Wk, Wv, q, k, v);
        attn_kernel<<<BB*NH, 256, ATT_SMEM>>>(q, k, v, att);
        gemm(att, Wo, Wob, x, x, MM, CC, CC, false, true);
        ln_kernel<<<MM/8, 256>>>(x, g2, bg2, h);
        gemm(h, W1, B1, nullptr, u, MM, FF, CC, true, false);
        gemm(u, W2, B2, x, x, MM, CC, FF, false, true);
    }

    ln_kernel<<<MM/8, 256>>>(x, lnf_g, lnf_b, h);
    gemm(h, lm_w, lm_b, nullptr, out, MM, VV, CC, false, false);
}

// round 4
// speedup vs baseline: 1.4261x; 1.4261x over previous
#include <cuda_runtime.h>
#include <math.h>
#include <stdint.h>

// Problem dims
#define BB 32
#define TT 256
#define CC 384
#define LL 6
#define NH 6
#define HD 64
#define VV 32000
#define MM (BB*TT)      // 8192
#define FF (4*CC)       // 1536

// Scratch (device globals; no allocations allowed)
__device__ float g_x[MM*CC];
__device__ float g_h[MM*CC];
__device__ float g_q[MM*CC];
__device__ float g_k[MM*CC];
__device__ float g_v[MM*CC];
__device__ float g_att[MM*CC];
__device__ float g_u[MM*FF];

// ---------------------------------------------------------------------------
// Helpers
// ---------------------------------------------------------------------------
__device__ __forceinline__ uint32_t f2tf(float f) {
    uint32_t u;
    asm("cvt.rna.tf32.f32 %0, %1;" : "=r"(u) : "f"(f));
    return u;
}

__device__ __forceinline__ void mma_tf32(float* c, const uint32_t* a, const uint32_t* b) {
    asm volatile(
        "mma.sync.aligned.m16n8k8.row.col.f32.tf32.tf32.f32 "
        "{%0,%1,%2,%3}, {%4,%5,%6,%7}, {%8,%9}, {%0,%1,%2,%3};"
        : "+f"(c[0]), "+f"(c[1]), "+f"(c[2]), "+f"(c[3])
        : "r"(a[0]), "r"(a[1]), "r"(a[2]), "r"(a[3]),
          "r"(b[0]), "r"(b[1]));
}

// ---------------------------------------------------------------------------
// Embedding
// ---------------------------------------------------------------------------
__global__ void embed_kernel(const int* __restrict__ idx,
                             const float* __restrict__ tok,
                             const float* __restrict__ pos,
                             float* __restrict__ X)
{
    int i = blockIdx.x * blockDim.x + threadIdx.x;
    if (i >= MM * (CC/4)) return;
    int row = i / (CC/4);
    int c4  = i % (CC/4);
    int t   = idx[row];
    int p   = row & (TT-1);
    float4 a = *(const float4*)(tok + (size_t)t*CC + c4*4);
    float4 e = *(const float4*)(pos + (size_t)p*CC + c4*4);
    a.x += e.x; a.y += e.y; a.z += e.z; a.w += e.w;
    *(float4*)(X + (size_t)row*CC + c4*4) = a;
}

// ---------------------------------------------------------------------------
// LayerNorm: one warp per row of 384
// ---------------------------------------------------------------------------
__global__ void ln_kernel(const float* __restrict__ X,
                          const float* __restrict__ g,
                          const float* __restrict__ b,
                          float* __restrict__ Y)
{
    int row  = blockIdx.x * 8 + (threadIdx.x >> 5);
    int lane = threadIdx.x & 31;
    if (row >= MM) return;
    const float* x = X + (size_t)row*CC;
    float v[12];
    float s = 0.f, ss = 0.f;
#pragma unroll
    for (int i = 0; i < 12; i++) {
        v[i] = x[lane + i*32];
        s  += v[i];
        ss += v[i]*v[i];
    }
#pragma unroll
    for (int o = 16; o; o >>= 1) {
        s  += __shfl_xor_sync(0xFFFFFFFFu, s,  o);
        ss += __shfl_xor_sync(0xFFFFFFFFu, ss, o);
    }
    float mean = s  * (1.0f/CC);
    float var  = ss * (1.0f/CC) - mean*mean;
    float inv  = rsqrtf(var + 1e-5f);
    float* y = Y + (size_t)row*CC;
#pragma unroll
    for (int i = 0; i < 12; i++) {
        int c = lane + i*32;
        y[c] = (v[i]-mean)*inv*g[c] + b[c];
    }
}

// ---------------------------------------------------------------------------
// TF32 tensor-core GEMM (round-2 proven version).
// Block tile 128x128, BK=32, 256 threads (8 warps), each warp 64x32.
// ---------------------------------------------------------------------------
template<bool RELU, bool RES>
__global__ __launch_bounds__(256)
void tgemm(const float* __restrict__ A, const float* __restrict__ B,
           const float* __restrict__ bias, const float* __restrict__ res,
           float* __restrict__ C, int M, int N, int K)
{
    __shared__ uint32_t As[128][36];
    __shared__ uint32_t Bs[32][136];

    const int bm = blockIdx.y * 128;
    const int bn = blockIdx.x * 128;
    const int tid  = threadIdx.x;
    const int lane = tid & 31;
    const int wid  = tid >> 5;
    const int wm = (wid & 1) * 64;
    const int wn = (wid >> 1) * 32;
    const int grp = lane >> 2;
    const int tg  = lane & 3;

    float acc[4][4][4];
#pragma unroll
    for (int mt = 0; mt < 4; mt++)
#pragma unroll
        for (int nt = 0; nt < 4; nt++)
#pragma unroll
            for (int e = 0; e < 4; e++) acc[mt][nt][e] = 0.f;

    for (int k0 = 0; k0 < K; k0 += 32) {
#pragma unroll
        for (int p = 0; p < 4; p++) {
            int i  = tid + p*256;
            int r  = i >> 3;
            int c4 = (i & 7) * 4;
            float4 v = *(const float4*)(A + (size_t)(bm + r)*K + k0 + c4);
            uint4 u;
            u.x = f2tf(v.x); u.y = f2tf(v.y); u.z = f2tf(v.z); u.w = f2tf(v.w);
            *(uint4*)&As[r][c4] = u;
        }
#pragma unroll
        for (int p = 0; p < 4; p++) {
            int i  = tid + p*256;
            int r  = i >> 5;
            int c4 = (i & 31) * 4;
            float4 v = *(const float4*)(B + (size_t)(k0 + r)*N + bn + c4);
            uint4 u;
            u.x = f2tf(v.x); u.y = f2tf(v.y); u.z = f2tf(v.z); u.w = f2tf(v.w);
            *(uint4*)&Bs[r][c4] = u;
        }
        __syncthreads();

#pragma unroll
        for (int kk = 0; kk < 32; kk += 8) {
            uint32_t af[4][4], bf[4][2];
#pragma unroll
            for (int mt = 0; mt < 4; mt++) {
                int r = wm + mt*16 + grp;
                af[mt][0] = As[r    ][kk + tg    ];
                af[mt][1] = As[r + 8][kk + tg    ];
                af[mt][2] = As[r    ][kk + tg + 4];
                af[mt][3] = As[r + 8][kk + tg + 4];
            }
#pragma unroll
            for (int nt = 0; nt < 4; nt++) {
                int c = wn + nt*8 + grp;
                bf[nt][0] = Bs[kk + tg    ][c];
                bf[nt][1] = Bs[kk + tg + 4][c];
            }
#pragma unroll
            for (int mt = 0; mt < 4; mt++)
#pragma unroll
                for (int nt = 0; nt < 4; nt++)
                    mma_tf32(acc[mt][nt], af[mt], bf[nt]);
        }
        __syncthreads();
    }

#pragma unroll
    for (int mt = 0; mt < 4; mt++) {
        int r0 = bm + wm + mt*16 + grp;
        int r1 = r0 + 8;
#pragma unroll
        for (int nt = 0; nt < 4; nt++) {
            int c = bn + wn + nt*8 + tg*2;
            float o0x = acc[mt][nt][0], o0y = acc[mt][nt][1];
            float o1x = acc[mt][nt][2], o1y = acc[mt][nt][3];
            if (bias) {
                float bv0 = bias[c], bv1 = bias[c+1];
                o0x += bv0; o0y += bv1; o1x += bv0; o1y += bv1;
            }
            if (RES) {
                float2 ra = *(const float2*)(res + (size_t)r0*N + c);
                float2 rb = *(const float2*)(res + (size_t)r1*N + c);
                o0x += ra.x; o0y += ra.y; o1x += rb.x; o1y += rb.y;
            }
            if (RELU) {
                o0x = fmaxf(o0x, 0.f); o0y = fmaxf(o0y, 0.f);
                o1x = fmaxf(o1x, 0.f); o1y = fmaxf(o1y, 0.f);
            }
            float2 w0 = {o0x, o0y};
            float2 w1 = {o1x, o1y};
            *(float2*)(C + (size_t)r0*N + c) = w0;
            *(float2*)(C + (size_t)r1*N + c) = w1;
        }
    }
}

// ---------------------------------------------------------------------------
// Tensor-core flash attention.
// 1 block per (b,h), 256 threads = 8 warps, warp w owns query rows [32w,32w+32).
// K/V staged in smem as tf32 (strides 68 / 72 -> conflict-free fragment LDS).
// Loop over 32-key chunks: S via m16n8k8 tf32, online softmax on fragments,
// P through per-warp smem (stride 36) to form A-fragments, then P@V mma.
// ---------------------------------------------------------------------------
#define AKS 68
#define AVS 72
#define APS 36
#define ATT_SMEM ((TT*AKS + TT*AVS + 8*32*APS) * (int)sizeof(uint32_t))

__global__ __launch_bounds__(256, 1)
void attn_mma(const float* __restrict__ Q, const float* __restrict__ K,
              const float* __restrict__ V, float* __restrict__ O)
{
    extern __shared__ uint32_t sm[];
    uint32_t* Ks = sm;
    uint32_t* Vs = sm + TT*AKS;
    uint32_t* Pb = sm + TT*AKS + TT*AVS;

    const int bh = blockIdx.x;
    const int b  = bh / NH;
    const int h  = bh % NH;
    const float scale = 0.05103103630798288f;  // 1/sqrt(384)

    const int tid = threadIdx.x;
    const float* kbase = K + (size_t)b*TT*CC + h*HD;
    const float* vbase = V + (size_t)b*TT*CC + h*HD;

    // stage K,V as tf32
    for (int i = tid; i < TT*16; i += 256) {
        int t  = i >> 4;
        int d4 = (i & 15) * 4;
        float4 kv = *(const float4*)(kbase + (size_t)t*CC + d4);
        uint4 u;
        u.x = f2tf(kv.x); u.y = f2tf(kv.y); u.z = f2tf(kv.z); u.w = f2tf(kv.w);
        *(uint4*)&Ks[t*AKS + d4] = u;
        float4 vv = *(const float4*)(vbase + (size_t)t*CC + d4);
        uint4 w;
        w.x = f2tf(vv.x); w.y = f2tf(vv.y); w.z = f2tf(vv.z); w.w = f2tf(vv.w);
        *(uint4*)&Vs[t*AVS + d4] = w;
    }
    __syncthreads();

    const int lane = tid & 31;
    const int w    = tid >> 5;
    const int grp  = lane >> 2;
    const int tg   = lane & 3;
    const int q0   = w * 32;

    // Q fragments: [mt][ks][4]
    const float* qbase = Q + (size_t)b*TT*CC + h*HD;
    uint32_t qa[2][8][4];
#pragma unroll
    for (int mt = 0; mt < 2; mt++) {
        int ra = q0 + mt*16 + grp;
        int rb = ra + 8;
#pragma unroll
        for (int ks = 0; ks < 8; ks++) {
            int d = ks*8 + tg;
            qa[mt][ks][0] = f2tf(qbase[(size_t)ra*CC + d    ]);
            qa[mt][ks][1] = f2tf(qbase[(size_t)rb*CC + d    ]);
            qa[mt][ks][2] = f2tf(qbase[(size_t)ra*CC + d + 4]);
            qa[mt][ks][3] = f2tf(qbase[(size_t)rb*CC + d + 4]);
        }
    }

    float o[2][8][4];
#pragma unroll
    for (int mt = 0; mt < 2; mt++)
#pragma unroll
        for (int nt = 0; nt < 8; nt++)
#pragma unroll
            for (int e = 0; e < 4; e++) o[mt][nt][e] = 0.f;

    float mrow[2][2] = {{-1e30f,-1e30f},{-1e30f,-1e30f}};
    float lrow[2][2] = {{0.f,0.f},{0.f,0.f}};

    uint32_t* myP = Pb + w * 32 * APS;

    for (int j = 0; j <= w; j++) {
        const int kbeg = j * 32;
        // ---- S = Q @ K^T for this 32-key chunk ----
        float s[2][4][4];
#pragma unroll
        for (int mt = 0; mt < 2; mt++)
#pragma unroll
            for (int nt = 0; nt < 4; nt++)
#pragma unroll
                for (int e = 0; e < 4; e++) s[mt][nt][e] = 0.f;

#pragma unroll
        for (int ks = 0; ks < 8; ks++) {
            uint32_t bf[4][2];
#pragma unroll
            for (int nt = 0; nt < 4; nt++) {
                int key = kbeg + nt*8 + grp;
                int d   = ks*8 + tg;
                bf[nt][0] = Ks[key*AKS + d    ];
                bf[nt][1] = Ks[key*AKS + d + 4];
            }
#pragma unroll
            for (int mt = 0; mt < 2; mt++)
#pragma unroll
                for (int nt = 0; nt < 4; nt++)
                    mma_tf32(s[mt][nt], qa[mt][ks], bf[nt]);
        }

        // ---- softmax (online) ----
#pragma unroll
        for (int mt = 0; mt < 2; mt++) {
            int ra = q0 + mt*16 + grp;      // row half 0
            int rb = ra + 8;                // row half 1
            float rmax0 = -1e30f, rmax1 = -1e30f;
#pragma unroll
            for (int nt = 0; nt < 4; nt++) {
                int c0 = kbeg + nt*8 + 2*tg;
#pragma unroll
                for (int e = 0; e < 4; e++) {
                    float vv = s[mt][nt][e] * scale;
                    int col = c0 + (e & 1);
                    int row = (e < 2) ? ra : rb;
                    if (j == w && col > row) vv = -1e30f;
                    s[mt][nt][e] = vv;
                }
                rmax0 = fmaxf(rmax0, fmaxf(s[mt][nt][0], s[mt][nt][1]));
                rmax1 = fmaxf(rmax1, fmaxf(s[mt][nt][2], s[mt][nt][3]));
            }
            rmax0 = fmaxf(rmax0, __shfl_xor_sync(0xFFFFFFFFu, rmax0, 1));
            rmax0 = fmaxf(rmax0, __shfl_xor_sync(0xFFFFFFFFu, rmax0, 2));
            rmax1 = fmaxf(rmax1, __shfl_xor_sync(0xFFFFFFFFu, rmax1, 1));
            rmax1 = fmaxf(rmax1, __shfl_xor_sync(0xFFFFFFFFu, rmax1, 2));

            float mn0 = fmaxf(mrow[mt][0], rmax0);
            float mn1 = fmaxf(mrow[mt][1], rmax1);
            float cr0 = __expf(mrow[mt][0] - mn0);
            float cr1 = __expf(mrow[mt][1] - mn1);
            mrow[mt][0] = mn0; mrow[mt][1] = mn1;

            float rs0 = 0.f, rs1 = 0.f;
#pragma unroll
            for (int nt = 0; nt < 4; nt++) {
                float p0 = __expf(s[mt][nt][0] - mn0);
                float p1 = __expf(s[mt][nt][1] - mn0);
                float p2 = __expf(s[mt][nt][2] - mn1);
                float p3 = __expf(s[mt][nt][3] - mn1);
                rs0 += p0 + p1; rs1 += p2 + p3;
                int cb = nt*8 + 2*tg;
                myP[(mt*16 + grp    )*APS + cb    ] = f2tf(p0);
                myP[(mt*16 + grp    )*APS + cb + 1] = f2tf(p1);
                myP[(mt*16 + grp + 8)*APS + cb    ] = f2tf(p2);
                myP[(mt*16 + grp + 8)*APS + cb + 1] = f2tf(p3);
            }
            rs0 += __shfl_xor_sync(0xFFFFFFFFu, rs0, 1);
            rs0 += __shfl_xor_sync(0xFFFFFFFFu, rs0, 2);
            rs1 += __shfl_xor_sync(0xFFFFFFFFu, rs1, 1);
            rs1 += __shfl_xor_sync(0xFFFFFFFFu, rs1, 2);
            lrow[mt][0] = lrow[mt][0]*cr0 + rs0;
            lrow[mt][1] = lrow[mt][1]*cr1 + rs1;
#pragma unroll
            for (int nt = 0; nt < 8; nt++) {
                o[mt][nt][0] *= cr0; o[mt][nt][1] *= cr0;
                o[mt][nt][2] *= cr1; o[mt][nt][3] *= cr1;
            }
        }
        __syncwarp();

        // ---- O += P @ V ----
#pragma unroll
        for (int ks2 = 0; ks2 < 4; ks2++) {
            uint32_t vb[8][2];
#pragma unroll
            for (int nt = 0; nt < 8; nt++) {
                int key = kbeg + ks2*8 + tg;
                int d   = nt*8 + grp;
                vb[nt][0] = Vs[ key     *AVS + d];
                vb[nt][1] = Vs[(key + 4)*AVS + d];
            }
#pragma unroll
            for (int mt = 0; mt < 2; mt++) {
                uint32_t pa[4];
                pa[0] = myP[(mt*16 + grp    )*APS + ks2*8 + tg    ];
                pa[1] = myP[(mt*16 + grp + 8)*APS + ks2*8 + tg    ];
                pa[2] = myP[(mt*16 + grp    )*APS + ks2*8 + tg + 4];
                pa[3] = myP[(mt*16 + grp + 8)*APS + ks2*8 + tg + 4];
#pragma unroll
                for (int nt = 0; nt < 8; nt++)
                    mma_tf32(o[mt][nt], pa, vb[nt]);
            }
        }
        __syncwarp();
    }

    // ---- epilogue: divide by l, store ----
    float* obase = O + (size_t)b*TT*CC + h*HD;
#pragma unroll
    for (int mt = 0; mt < 2; mt++) {
        int ra = q0 + mt*16 + grp;
        int rb = ra + 8;
        float inv0 = 1.f / lrow[mt][0];
        float inv1 = 1.f / lrow[mt][1];
#pragma unroll
        for (int nt = 0; nt < 8; nt++) {
            int d = nt*8 + 2*tg;
            float2 w0 = {o[mt][nt][0]*inv0, o[mt][nt][1]*inv0};
            float2 w1 = {o[mt][nt][2]*inv1, o[mt][nt][3]*inv1};
            *(float2*)(obase + (size_t)ra*CC + d) = w0;
            *(float2*)(obase + (size_t)rb*CC + d) = w1;
        }
    }
}

// ---------------------------------------------------------------------------
// Host
// ---------------------------------------------------------------------------
static void gemm(const float* A, const float* B, const float* bias, const float* res,
                 float* C, int M, int N, int K, bool relu, bool hasRes)
{
    dim3 grid(N/128, M/128);
    if (relu)        tgemm<true,  false><<<grid, 256>>>(A, B, bias, res, C, M, N, K);
    else if (hasRes) tgemm<false, true ><<<grid, 256>>>(A, B, bias, res, C, M, N, K);
    else             tgemm<false, false><<<grid, 256>>>(A, B, bias, res, C, M, N, K);
}

extern "C" void kernel_launch(void* const* d_in, const int* in_sizes, int n_in,
                              void* d_out, int out_size)
{
    (void)in_sizes; (void)n_in; (void)out_size;

    const int*   idx     = (const int*)  d_in[0];
    const float* tok_emb = (const float*)d_in[1];
    const float* pos_emb = (const float*)d_in[2];
    const float* ln1_g   = (const float*)d_in[3];
    const float* ln1_b   = (const float*)d_in[4];
    const float* wq      = (const float*)d_in[5];
    const float* wk      = (const float*)d_in[6];
    const float* wv      = (const float*)d_in[7];
    const float* wo      = (const float*)d_in[8];
    const float* wo_b    = (const float*)d_in[9];
    const float* ln2_g   = (const float*)d_in[10];
    const float* ln2_b   = (const float*)d_in[11];
    const float* w1      = (const float*)d_in[12];
    const float* b1      = (const float*)d_in[13];
    const float* w2      = (const float*)d_in[14];
    const float* b2      = (const float*)d_in[15];
    const float* lnf_g   = (const float*)d_in[16];
    const float* lnf_b   = (const float*)d_in[17];
    const float* lm_w    = (const float*)d_in[18];
    const float* lm_b    = (const float*)d_in[19];
    float* out = (float*)d_out;

    float *x, *h, *q, *k, *v, *att, *u;
    cudaGetSymbolAddress((void**)&x,   g_x);
    cudaGetSymbolAddress((void**)&h,   g_h);
    cudaGetSymbolAddress((void**)&q,   g_q);
    cudaGetSymbolAddress((void**)&k,   g_k);
    cudaGetSymbolAddress((void**)&v,   g_v);
    cudaGetSymbolAddress((void**)&att, g_att);
    cudaGetSymbolAddress((void**)&u,   g_u);

    cudaFuncSetAttribute(attn_mma, cudaFuncAttributeMaxDynamicSharedMemorySize, ATT_SMEM);

    {
        int total = MM * (CC/4);
        embed_kernel<<<(total + 255)/256, 256>>>(idx, tok_emb, pos_emb, x);
    }

    for (int L = 0; L < LL; L++) {
        const float* g1  = ln1_g + (size_t)L*CC;
        const float* bg1 = ln1_b + (size_t)L*CC;
        const float* Wq  = wq   + (size_t)L*CC*CC;
        const float* Wk  = wk   + (size_t)L*CC*CC;
        const float* Wv  = wv   + (size_t)L*CC*CC;
        const float* Wo  = wo   + (size_t)L*CC*CC;
        const float* Wob = wo_b + (size_t)L*CC;
        const float* g2  = ln2_g + (size_t)L*CC;
        const float* bg2 = ln2_b + (size_t)L*CC;
        const float* W1  = w1 + (size_t)L*CC*FF;
        const float* B1  = b1 + (size_t)L*FF;
        const float* W2  = w2 + (size_t)L*FF*CC;
        const float* B2  = b2 + (size_t)L*CC;

        ln_kernel<<<MM/8, 256>>>(x, g1, bg1, h);
        gemm(h, Wq, nullptr, nullptr, q, MM, CC, CC, false, false);
        gemm(h, Wk, nullptr, nullptr, k, MM, CC, CC, false, false);
        gemm(h, Wv, nullptr, nullptr, v, MM, CC, CC, false, false);
        attn_mma<<<BB*NH, 256, ATT_SMEM>>>(q, k, v, att);
        gemm(att, Wo, Wob, x, x, MM, CC, CC, false, true);
        ln_kernel<<<MM/8, 256>>>(x, g2, bg2, h);
        gemm(h, W1, B1, nullptr, u, MM, FF, CC, true, false);
        gemm(u, W2, B2, x, x, MM, CC, FF, false, true);
    }

    ln_kernel<<<MM/8, 256>>>(x, lnf_g, lnf_b, h);
    gemm(h, lm_w, lm_b, nullptr, out, MM, VV, CC, false, false);
}

// round 5
// speedup vs baseline: 1.4707x; 1.0313x over previous
#include <cuda_runtime.h>
#include <math.h>
#include <stdint.h>

// Problem dims
#define BB 32
#define TT 256
#define CC 384
#define LL 6
#define NH 6
#define HD 64
#define VV 32000
#define MM (BB*TT)      // 8192
#define FF (4*CC)       // 1536

// Scratch (device globals; no allocations allowed)
__device__ float g_x[MM*CC];
__device__ float g_h[MM*CC];
__device__ float g_q[MM*CC];
__device__ float g_k[MM*CC];
__device__ float g_v[MM*CC];
__device__ float g_att[MM*CC];
__device__ float g_u[MM*FF];

// ---------------------------------------------------------------------------
// Helpers
// ---------------------------------------------------------------------------
__device__ __forceinline__ uint32_t f2tf(float f) {
    uint32_t u;
    asm("cvt.rna.tf32.f32 %0, %1;" : "=r"(u) : "f"(f));
    return u;
}

__device__ __forceinline__ void mma_tf32(float* c, const uint32_t* a, const uint32_t* b) {
    asm volatile(
        "mma.sync.aligned.m16n8k8.row.col.f32.tf32.tf32.f32 "
        "{%0,%1,%2,%3}, {%4,%5,%6,%7}, {%8,%9}, {%0,%1,%2,%3};"
        : "+f"(c[0]), "+f"(c[1]), "+f"(c[2]), "+f"(c[3])
        : "r"(a[0]), "r"(a[1]), "r"(a[2]), "r"(a[3]),
          "r"(b[0]), "r"(b[1]));
}

__device__ __forceinline__ void cp_async16(void* sptr, const void* gptr) {
    uint32_t sa = (uint32_t)__cvta_generic_to_shared(sptr);
    asm volatile("cp.async.cg.shared.global [%0], [%1], 16;\n" :: "r"(sa), "l"(gptr));
}
#define CP_COMMIT() asm volatile("cp.async.commit_group;\n" ::: "memory")
#define CP_WAIT0()  asm volatile("cp.async.wait_group 0;\n" ::: "memory")

// ---------------------------------------------------------------------------
// Embedding
// ---------------------------------------------------------------------------
__global__ void embed_kernel(const int* __restrict__ idx,
                             const float* __restrict__ tok,
                             const float* __restrict__ pos,
                             float* __restrict__ X)
{
    int i = blockIdx.x * blockDim.x + threadIdx.x;
    if (i >= MM * (CC/4)) return;
    int row = i / (CC/4);
    int c4  = i % (CC/4);
    int t   = idx[row];
    int p   = row & (TT-1);
    float4 a = *(const float4*)(tok + (size_t)t*CC + c4*4);
    float4 e = *(const float4*)(pos + (size_t)p*CC + c4*4);
    a.x += e.x; a.y += e.y; a.z += e.z; a.w += e.w;
    *(float4*)(X + (size_t)row*CC + c4*4) = a;
}

// ---------------------------------------------------------------------------
// LayerNorm: one warp per row of 384
// ---------------------------------------------------------------------------
__global__ void ln_kernel(const float* __restrict__ X,
                          const float* __restrict__ g,
                          const float* __restrict__ b,
                          float* __restrict__ Y)
{
    int row  = blockIdx.x * 8 + (threadIdx.x >> 5);
    int lane = threadIdx.x & 31;
    if (row >= MM) return;
    const float* x = X + (size_t)row*CC;
    float v[12];
    float s = 0.f, ss = 0.f;
#pragma unroll
    for (int i = 0; i < 12; i++) {
        v[i] = x[lane + i*32];
        s  += v[i];
        ss += v[i]*v[i];
    }
#pragma unroll
    for (int o = 16; o; o >>= 1) {
        s  += __shfl_xor_sync(0xFFFFFFFFu, s,  o);
        ss += __shfl_xor_sync(0xFFFFFFFFu, ss, o);
    }
    float mean = s  * (1.0f/CC);
    float var  = ss * (1.0f/CC) - mean*mean;
    float inv  = rsqrtf(var + 1e-5f);
    float* y = Y + (size_t)row*CC;
#pragma unroll
    for (int i = 0; i < 12; i++) {
        int c = lane + i*32;
        y[c] = (v[i]-mean)*inv*g[c] + b[c];
    }
}

// ---------------------------------------------------------------------------
// TF32 GEMM core: 128x128 tile, BK=32, cp.async double-buffered smem.
// 256 threads, 8 warps each 64x32 via m16n8k8. f32 in smem, cvt at frag load.
// ---------------------------------------------------------------------------
struct GemmSmem {
    float As[2][128][36];
    float Bs[2][32][136];
};
#define SMEM_GEMM ((int)sizeof(GemmSmem))   // 71680 bytes

template<bool RELU, bool RES>
__device__ __forceinline__
void gemm_core(GemmSmem* sm,
               const float* __restrict__ A, const float* __restrict__ B,
               const float* __restrict__ bias, const float* __restrict__ res,
               float* __restrict__ C, int M, int N, int K, int bm, int bn)
{
    const int tid  = threadIdx.x;
    const int lane = tid & 31;
    const int wid  = tid >> 5;
    const int wm = (wid & 1) * 64;
    const int wn = (wid >> 1) * 32;
    const int grp = lane >> 2;
    const int tg  = lane & 3;

    float acc[4][4][4];
#pragma unroll
    for (int mt = 0; mt < 4; mt++)
#pragma unroll
        for (int nt = 0; nt < 4; nt++)
#pragma unroll
            for (int e = 0; e < 4; e++) acc[mt][nt][e] = 0.f;

    auto issue = [&](int s, int k0) {
#pragma unroll
        for (int p = 0; p < 4; p++) {
            int i  = tid + p*256;
            int r  = i >> 3;
            int c4 = (i & 7) * 4;
            cp_async16(&sm->As[s][r][c4], A + (size_t)(bm + r)*K + k0 + c4);
        }
#pragma unroll
        for (int p = 0; p < 4; p++) {
            int i  = tid + p*256;
            int r  = i >> 5;
            int c4 = (i & 31) * 4;
            cp_async16(&sm->Bs[s][r][c4], B + (size_t)(k0 + r)*N + bn + c4);
        }
        CP_COMMIT();
    };

    const int nIter = K >> 5;
    issue(0, 0);

    for (int it = 0; it < nIter; it++) {
        const int cur = it & 1;
        CP_WAIT0();
        __syncthreads();
        if (it + 1 < nIter) issue(cur ^ 1, (it + 1) << 5);

#pragma unroll
        for (int kk = 0; kk < 32; kk += 8) {
            uint32_t af[4][4], bf[4][2];
#pragma unroll
            for (int mt = 0; mt < 4; mt++) {
                int r = wm + mt*16 + grp;
                af[mt][0] = f2tf(sm->As[cur][r    ][kk + tg    ]);
                af[mt][1] = f2tf(sm->As[cur][r + 8][kk + tg    ]);
                af[mt][2] = f2tf(sm->As[cur][r    ][kk + tg + 4]);
                af[mt][3] = f2tf(sm->As[cur][r + 8][kk + tg + 4]);
            }
#pragma unroll
            for (int nt = 0; nt < 4; nt++) {
                int c = wn + nt*8 + grp;
                bf[nt][0] = f2tf(sm->Bs[cur][kk + tg    ][c]);
                bf[nt][1] = f2tf(sm->Bs[cur][kk + tg + 4][c]);
            }
#pragma unroll
            for (int mt = 0; mt < 4; mt++)
#pragma unroll
                for (int nt = 0; nt < 4; nt++)
                    mma_tf32(acc[mt][nt], af[mt], bf[nt]);
        }
        __syncthreads();
    }

    // Epilogue
#pragma unroll
    for (int mt = 0; mt < 4; mt++) {
        int r0 = bm + wm + mt*16 + grp;
        int r1 = r0 + 8;
#pragma unroll
        for (int nt = 0; nt < 4; nt++) {
            int c = bn + wn + nt*8 + tg*2;
            float o0x = acc[mt][nt][0], o0y = acc[mt][nt][1];
            float o1x = acc[mt][nt][2], o1y = acc[mt][nt][3];
            if (bias) {
                float bv0 = bias[c], bv1 = bias[c+1];
                o0x += bv0; o0y += bv1; o1x += bv0; o1y += bv1;
            }
            if (RES) {
                float2 ra = *(const float2*)(res + (size_t)r0*N + c);
                float2 rb = *(const float2*)(res + (size_t)r1*N + c);
                o0x += ra.x; o0y += ra.y; o1x += rb.x; o1y += rb.y;
            }
            if (RELU) {
                o0x = fmaxf(o0x, 0.f); o0y = fmaxf(o0y, 0.f);
                o1x = fmaxf(o1x, 0.f); o1y = fmaxf(o1y, 0.f);
            }
            float2 w0 = {o0x, o0y};
            float2 w1 = {o1x, o1y};
            *(float2*)(C + (size_t)r0*N + c) = w0;
            *(float2*)(C + (size_t)r1*N + c) = w1;
        }
    }
}

template<bool RELU, bool RES>
__global__ __launch_bounds__(256)
void tgemm(const float* __restrict__ A, const float* __restrict__ B,
           const float* __restrict__ bias, const float* __restrict__ res,
           float* __restrict__ C, int M, int N, int K)
{
    extern __shared__ GemmSmem smg[];
    gemm_core<RELU, RES>(smg, A, B, bias, res, C, M, N, K,
                         blockIdx.y * 128, blockIdx.x * 128);
}

// Fused QKV: grid.x = 9 (3 matrices x 3 col-tiles), grid.y = 64.
__global__ __launch_bounds__(256)
void qkv_gemm(const float* __restrict__ A,
              const float* __restrict__ Wq, const float* __restrict__ Wk,
              const float* __restrict__ Wv,
              float* __restrict__ Q, float* __restrict__ Ko, float* __restrict__ V)
{
    extern __shared__ GemmSmem smg[];
    int sel = blockIdx.x / 3;
    int bn  = (blockIdx.x % 3) * 128;
    const float* B = (sel == 0) ? Wq : (sel == 1) ? Wk : Wv;
    float*       C = (sel == 0) ? Q  : (sel == 1) ? Ko : V;
    gemm_core<false, false>(smg, A, B, nullptr, nullptr, C,
                            MM, CC, CC, blockIdx.y * 128, bn);
}

// ---------------------------------------------------------------------------
// Tensor-core flash attention (round-4 proven version).
// ---------------------------------------------------------------------------
#define AKS 68
#define AVS 72
#define APS 36
#define ATT_SMEM ((TT*AKS + TT*AVS + 8*32*APS) * (int)sizeof(uint32_t))

__global__ __launch_bounds__(256, 1)
void attn_mma(const float* __restrict__ Q, const float* __restrict__ K,
              const float* __restrict__ V, float* __restrict__ O)
{
    extern __shared__ uint32_t sm[];
    uint32_t* Ks = sm;
    uint32_t* Vs = sm + TT*AKS;
    uint32_t* Pb = sm + TT*AKS + TT*AVS;

    const int bh = blockIdx.x;
    const int b  = bh / NH;
    const int h  = bh % NH;
    const float scale = 0.05103103630798288f;  // 1/sqrt(384)

    const int tid = threadIdx.x;
    const float* kbase = K + (size_t)b*TT*CC + h*HD;
    const float* vbase = V + (size_t)b*TT*CC + h*HD;

    for (int i = tid; i < TT*16; i += 256) {
        int t  = i >> 4;
        int d4 = (i & 15) * 4;
        float4 kv = *(const float4*)(kbase + (size_t)t*CC + d4);
        uint4 u;
        u.x = f2tf(kv.x); u.y = f2tf(kv.y); u.z = f2tf(kv.z); u.w = f2tf(kv.w);
        *(uint4*)&Ks[t*AKS + d4] = u;
        float4 vv = *(const float4*)(vbase + (size_t)t*CC + d4);
        uint4 w;
        w.x = f2tf(vv.x); w.y = f2tf(vv.y); w.z = f2tf(vv.z); w.w = f2tf(vv.w);
        *(uint4*)&Vs[t*AVS + d4] = w;
    }
    __syncthreads();

    const int lane = tid & 31;
    const int w    = tid >> 5;
    const int grp  = lane >> 2;
    const int tg   = lane & 3;
    const int q0   = w * 32;

    const float* qbase = Q + (size_t)b*TT*CC + h*HD;
    uint32_t qa[2][8][4];
#pragma unroll
    for (int mt = 0; mt < 2; mt++) {
        int ra = q0 + mt*16 + grp;
        int rb = ra + 8;
#pragma unroll
        for (int ks = 0; ks < 8; ks++) {
            int d = ks*8 + tg;
            qa[mt][ks][0] = f2tf(qbase[(size_t)ra*CC + d    ]);
            qa[mt][ks][1] = f2tf(qbase[(size_t)rb*CC + d    ]);
            qa[mt][ks][2] = f2tf(qbase[(size_t)ra*CC + d + 4]);
            qa[mt][ks][3] = f2tf(qbase[(size_t)rb*CC + d + 4]);
        }
    }

    float o[2][8][4];
#pragma unroll
    for (int mt = 0; mt < 2; mt++)
#pragma unroll
        for (int nt = 0; nt < 8; nt++)
#pragma unroll
            for (int e = 0; e < 4; e++) o[mt][nt][e] = 0.f;

    float mrow[2][2] = {{-1e30f,-1e30f},{-1e30f,-1e30f}};
    float lrow[2][2] = {{0.f,0.f},{0.f,0.f}};

    uint32_t* myP = Pb + w * 32 * APS;

    for (int j = 0; j <= w; j++) {
        const int kbeg = j * 32;
        float s[2][4][4];
#pragma unroll
        for (int mt = 0; mt < 2; mt++)
#pragma unroll
            for (int nt = 0; nt < 4; nt++)
#pragma unroll
                for (int e = 0; e < 4; e++) s[mt][nt][e] = 0.f;

#pragma unroll
        for (int ks = 0; ks < 8; ks++) {
            uint32_t bf[4][2];
#pragma unroll
            for (int nt = 0; nt < 4; nt++) {
                int key = kbeg + nt*8 + grp;
                int d   = ks*8 + tg;
                bf[nt][0] = Ks[key*AKS + d    ];
                bf[nt][1] = Ks[key*AKS + d + 4];
            }
#pragma unroll
            for (int mt = 0; mt < 2; mt++)
#pragma unroll
                for (int nt = 0; nt < 4; nt++)
                    mma_tf32(s[mt][nt], qa[mt][ks], bf[nt]);
        }

#pragma unroll
        for (int mt = 0; mt < 2; mt++) {
            int ra = q0 + mt*16 + grp;
            int rb = ra + 8;
            float rmax0 = -1e30f, rmax1 = -1e30f;
#pragma unroll
            for (int nt = 0; nt < 4; nt++) {
                int c0 = kbeg + nt*8 + 2*tg;
#pragma unroll
                for (int e = 0; e < 4; e++) {
                    float vv = s[mt][nt][e] * scale;
                    int col = c0 + (e & 1);
                    int row = (e < 2) ? ra : rb;
                    if (j == w && col > row) vv = -1e30f;
                    s[mt][nt][e] = vv;
                }
                rmax0 = fmaxf(rmax0, fmaxf(s[mt][nt][0], s[mt][nt][1]));
                rmax1 = fmaxf(rmax1, fmaxf(s[mt][nt][2], s[mt][nt][3]));
            }
            rmax0 = fmaxf(rmax0, __shfl_xor_sync(0xFFFFFFFFu, rmax0, 1));
            rmax0 = fmaxf(rmax0, __shfl_xor_sync(0xFFFFFFFFu, rmax0, 2));
            rmax1 = fmaxf(rmax1, __shfl_xor_sync(0xFFFFFFFFu, rmax1, 1));
            rmax1 = fmaxf(rmax1, __shfl_xor_sync(0xFFFFFFFFu, rmax1, 2));

            float mn0 = fmaxf(mrow[mt][0], rmax0);
            float mn1 = fmaxf(mrow[mt][1], rmax1);
            float cr0 = __expf(mrow[mt][0] - mn0);
            float cr1 = __expf(mrow[mt][1] - mn1);
            mrow[mt][0] = mn0; mrow[mt][1] = mn1;

            float rs0 = 0.f, rs1 = 0.f;
#pragma unroll
            for (int nt = 0; nt < 4; nt++) {
                float p0 = __expf(s[mt][nt][0] - mn0);
                float p1 = __expf(s[mt][nt][1] - mn0);
                float p2 = __expf(s[mt][nt][2] - mn1);
                float p3 = __expf(s[mt][nt][3] - mn1);
                rs0 += p0 + p1; rs1 += p2 + p3;
                int cb = nt*8 + 2*tg;
                myP[(mt*16 + grp    )*APS + cb    ] = f2tf(p0);
                myP[(mt*16 + grp    )*APS + cb + 1] = f2tf(p1);
                myP[(mt*16 + grp + 8)*APS + cb    ] = f2tf(p2);
                myP[(mt*16 + grp + 8)*APS + cb + 1] = f2tf(p3);
            }
            rs0 += __shfl_xor_sync(0xFFFFFFFFu, rs0, 1);
            rs0 += __shfl_xor_sync(0xFFFFFFFFu, rs0, 2);
            rs1 += __shfl_xor_sync(0xFFFFFFFFu, rs1, 1);
            rs1 += __shfl_xor_sync(0xFFFFFFFFu, rs1, 2);
            lrow[mt][0] = lrow[mt][0]*cr0 + rs0;
            lrow[mt][1] = lrow[mt][1]*cr1 + rs1;
#pragma unroll
            for (int nt = 0; nt < 8; nt++) {
                o[mt][nt][0] *= cr0; o[mt][nt][1] *= cr0;
                o[mt][nt][2] *= cr1; o[mt][nt][3] *= cr1;
            }
        }
        __syncwarp();

#pragma unroll
        for (int ks2 = 0; ks2 < 4; ks2++) {
            uint32_t vb[8][2];
#pragma unroll
            for (int nt = 0; nt < 8; nt++) {
                int key = kbeg + ks2*8 + tg;
                int d   = nt*8 + grp;
                vb[nt][0] = Vs[ key     *AVS + d];
                vb[nt][1] = Vs[(key + 4)*AVS + d];
            }
#pragma unroll
            for (int mt = 0; mt < 2; mt++) {
                uint32_t pa[4];
                pa[0] = myP[(mt*16 + grp    )*APS + ks2*8 + tg    ];
                pa[1] = myP[(mt*16 + grp + 8)*APS + ks2*8 + tg    ];
                pa[2] = myP[(mt*16 + grp    )*APS + ks2*8 + tg + 4];
                pa[3] = myP[(mt*16 + grp + 8)*APS + ks2*8 + tg + 4];
#pragma unroll
                for (int nt = 0; nt < 8; nt++)
                    mma_tf32(o[mt][nt], pa, vb[nt]);
            }
        }
        __syncwarp();
    }

    float* obase = O + (size_t)b*TT*CC + h*HD;
#pragma unroll
    for (int mt = 0; mt < 2; mt++) {
        int ra = q0 + mt*16 + grp;
        int rb = ra + 8;
        float inv0 = 1.f / lrow[mt][0];
        float inv1 = 1.f / lrow[mt][1];
#pragma unroll
        for (int nt = 0; nt < 8; nt++) {
            int d = nt*8 + 2*tg;
            float2 w0 = {o[mt][nt][0]*inv0, o[mt][nt][1]*inv0};
            float2 w1 = {o[mt][nt][2]*inv1, o[mt][nt][3]*inv1};
            *(float2*)(obase + (size_t)ra*CC + d) = w0;
            *(float2*)(obase + (size_t)rb*CC + d) = w1;
        }
    }
}

// ---------------------------------------------------------------------------
// Host
// ---------------------------------------------------------------------------
static void gemm(const float* A, const float* B, const float* bias, const float* res,
                 float* C, int M, int N, int K, bool relu, bool hasRes)
{
    dim3 grid(N/128, M/128);
    if (relu)        tgemm<true,  false><<<grid, 256, SMEM_GEMM>>>(A, B, bias, res, C, M, N, K);
    else if (hasRes) tgemm<false, true ><<<grid, 256, SMEM_GEMM>>>(A, B, bias, res, C, M, N, K);
    else             tgemm<false, false><<<grid, 256, SMEM_GEMM>>>(A, B, bias, res, C, M, N, K);
}

extern "C" void kernel_launch(void* const* d_in, const int* in_sizes, int n_in,
                              void* d_out, int out_size)
{
    (void)in_sizes; (void)n_in; (void)out_size;

    const int*   idx     = (const int*)  d_in[0];
    const float* tok_emb = (const float*)d_in[1];
    const float* pos_emb = (const float*)d_in[2];
    const float* ln1_g   = (const float*)d_in[3];
    const float* ln1_b   = (const float*)d_in[4];
    const float* wq      = (const float*)d_in[5];
    const float* wk      = (const float*)d_in[6];
    const float* wv      = (const float*)d_in[7];
    const float* wo      = (const float*)d_in[8];
    const float* wo_b    = (const float*)d_in[9];
    const float* ln2_g   = (const float*)d_in[10];
    const float* ln2_b   = (const float*)d_in[11];
    const float* w1      = (const float*)d_in[12];
    const float* b1      = (const float*)d_in[13];
    const float* w2      = (const float*)d_in[14];
    const float* b2      = (const float*)d_in[15];
    const float* lnf_g   = (const float*)d_in[16];
    const float* lnf_b   = (const float*)d_in[17];
    const float* lm_w    = (const float*)d_in[18];
    const float* lm_b    = (const float*)d_in[19];
    float* out = (float*)d_out;

    float *x, *h, *q, *k, *v, *att, *u;
    cudaGetSymbolAddress((void**)&x,   g_x);
    cudaGetSymbolAddress((void**)&h,   g_h);
    cudaGetSymbolAddress((void**)&q,   g_q);
    cudaGetSymbolAddress((void**)&k,   g_k);
    cudaGetSymbolAddress((void**)&v,   g_v);
    cudaGetSymbolAddress((void**)&att, g_att);
    cudaGetSymbolAddress((void**)&u,   g_u);

    cudaFuncSetAttribute(attn_mma, cudaFuncAttributeMaxDynamicSharedMemorySize, ATT_SMEM);
    cudaFuncSetAttribute(tgemm<false,false>, cudaFuncAttributeMaxDynamicSharedMemorySize, SMEM_GEMM);
    cudaFuncSetAttribute(tgemm<false,true >, cudaFuncAttributeMaxDynamicSharedMemorySize, SMEM_GEMM);
    cudaFuncSetAttribute(tgemm<true ,false>, cudaFuncAttributeMaxDynamicSharedMemorySize, SMEM_GEMM);
    cudaFuncSetAttribute(qkv_gemm,           cudaFuncAttributeMaxDynamicSharedMemorySize, SMEM_GEMM);

    {
        int total = MM * (CC/4);
        embed_kernel<<<(total + 255)/256, 256>>>(idx, tok_emb, pos_emb, x);
    }

    for (int L = 0; L < LL; L++) {
        const float* g1  = ln1_g + (size_t)L*CC;
        const float* bg1 = ln1_b + (size_t)L*CC;
        const float* Wq  = wq   + (size_t)L*CC*CC;
        const float* Wk  = wk   + (size_t)L*CC*CC;
        const float* Wv  = wv   + (size_t)L*CC*CC;
        const float* Wo  = wo   + (size_t)L*CC*CC;
        const float* Wob = wo_b + (size_t)L*CC;
        const float* g2  = ln2_g + (size_t)L*CC;
        const float* bg2 = ln2_b + (size_t)L*CC;
        const float* W1  = w1 + (size_t)L*CC*FF;
        const float* B1  = b1 + (size_t)L*FF;
        const float* W2  = w2 + (size_t)L*FF*CC;
        const float* B2  = b2 + (size_t)L*CC;

        ln_kernel<<<MM/8, 256>>>(x, g1, bg1, h);
        qkv_gemm<<<dim3(9, 64), 256, SMEM_GEMM>>>(h, Wq, Wk, Wv, q, k, v);
        attn_mma<<<BB*NH, 256, ATT_SMEM>>>(q, k, v, att);
        gemm(att, Wo, Wob, x, x, MM, CC, CC, false, true);
        ln_kernel<<<MM/8, 256>>>(x, g2, bg2, h);
        gemm(h, W1, B1, nullptr, u, MM, FF, CC, true, false);
        gemm(u, W2, B2, x, x, MM, CC, FF, false, true);
    }

    ln_kernel<<<MM/8, 256>>>(x, lnf_g, lnf_b, h);
    gemm(h, lm_w, lm_b, nullptr, out, MM, VV, CC, false, false);
}

// round 6
// speedup vs baseline: 1.6704x; 1.1358x over previous
#include <cuda_runtime.h>
#include <math.h>
#include <stdint.h>

// Problem dims
#define BB 32
#define TT 256
#define CC 384
#define LL 6
#define NH 6
#define HD 64
#define VV 32000
#define MM (BB*TT)      // 8192
#define FF (4*CC)       // 1536

// tf32 weight scratch layout (element offsets)
#define OFF_WQ 0
#define OFF_WK 884736
#define OFF_WV 1769472
#define OFF_WO 2654208
#define OFF_W1 3538944
#define OFF_W2 7077888
#define OFF_LM 10616832
#define WT_TOTAL 22904832

// Scratch (device globals; no allocations allowed)
__device__ float    g_x[MM*CC];          // residual stream (f32)
__device__ uint32_t g_h[MM*CC];          // LN output (tf32)
__device__ uint32_t g_q[MM*CC];
__device__ uint32_t g_k[MM*CC];
__device__ uint32_t g_v[MM*CC];
__device__ uint32_t g_att[MM*CC];
__device__ uint32_t g_u[MM*FF];
__device__ uint32_t g_wt[WT_TOTAL];      // tf32 weights

// ---------------------------------------------------------------------------
// Helpers
// ---------------------------------------------------------------------------
__device__ __forceinline__ uint32_t f2tf(float f) {
    uint32_t u;
    asm("cvt.rna.tf32.f32 %0, %1;" : "=r"(u) : "f"(f));
    return u;
}

__device__ __forceinline__ void mma_tf32(float* c, const uint32_t* a, const uint32_t* b) {
    asm volatile(
        "mma.sync.aligned.m16n8k8.row.col.f32.tf32.tf32.f32 "
        "{%0,%1,%2,%3}, {%4,%5,%6,%7}, {%8,%9}, {%0,%1,%2,%3};"
        : "+f"(c[0]), "+f"(c[1]), "+f"(c[2]), "+f"(c[3])
        : "r"(a[0]), "r"(a[1]), "r"(a[2]), "r"(a[3]),
          "r"(b[0]), "r"(b[1]));
}

__device__ __forceinline__ void cp_async16(void* sptr, const void* gptr) {
    uint32_t sa = (uint32_t)__cvta_generic_to_shared(sptr);
    asm volatile("cp.async.cg.shared.global [%0], [%1], 16;\n" :: "r"(sa), "l"(gptr));
}
#define CP_COMMIT() asm volatile("cp.async.commit_group;\n" ::: "memory")
#define CP_WAIT0()  asm volatile("cp.async.wait_group 0;\n" ::: "memory")

// ---------------------------------------------------------------------------
// f32 -> tf32 conversion (vectorized by 4)
// ---------------------------------------------------------------------------
__global__ void cvt_kernel(const float* __restrict__ src, uint32_t* __restrict__ dst, int n4)
{
    int i = blockIdx.x * blockDim.x + threadIdx.x;
    if (i >= n4) return;
    float4 v = *(const float4*)(src + (size_t)i*4);
    uint4 u;
    u.x = f2tf(v.x); u.y = f2tf(v.y); u.z = f2tf(v.z); u.w = f2tf(v.w);
    *(uint4*)(dst + (size_t)i*4) = u;
}

// ---------------------------------------------------------------------------
// Embedding (f32 residual stream)
// ---------------------------------------------------------------------------
__global__ void embed_kernel(const int* __restrict__ idx,
                             const float* __restrict__ tok,
                             const float* __restrict__ pos,
                             float* __restrict__ X)
{
    int i = blockIdx.x * blockDim.x + threadIdx.x;
    if (i >= MM * (CC/4)) return;
    int row = i / (CC/4);
    int c4  = i % (CC/4);
    int t   = idx[row];
    int p   = row & (TT-1);
    float4 a = *(const float4*)(tok + (size_t)t*CC + c4*4);
    float4 e = *(const float4*)(pos + (size_t)p*CC + c4*4);
    a.x += e.x; a.y += e.y; a.z += e.z; a.w += e.w;
    *(float4*)(X + (size_t)row*CC + c4*4) = a;
}

// ---------------------------------------------------------------------------
// LayerNorm: one warp per row; output tf32
// ---------------------------------------------------------------------------
__global__ void ln_kernel(const float* __restrict__ X,
                          const float* __restrict__ g,
                          const float* __restrict__ b,
                          uint32_t* __restrict__ Y)
{
    int row  = blockIdx.x * 8 + (threadIdx.x >> 5);
    int lane = threadIdx.x & 31;
    if (row >= MM) return;
    const float* x = X + (size_t)row*CC;
    float v[12];
    float s = 0.f, ss = 0.f;
#pragma unroll
    for (int i = 0; i < 12; i++) {
        v[i] = x[lane + i*32];
        s  += v[i];
        ss += v[i]*v[i];
    }
#pragma unroll
    for (int o = 16; o; o >>= 1) {
        s  += __shfl_xor_sync(0xFFFFFFFFu, s,  o);
        ss += __shfl_xor_sync(0xFFFFFFFFu, ss, o);
    }
    float mean = s  * (1.0f/CC);
    float var  = ss * (1.0f/CC) - mean*mean;
    float inv  = rsqrtf(var + 1e-5f);
    uint32_t* y = Y + (size_t)row*CC;
#pragma unroll
    for (int i = 0; i < 12; i++) {
        int c = lane + i*32;
        y[c] = f2tf((v[i]-mean)*inv*g[c] + b[c]);
    }
}

// ---------------------------------------------------------------------------
// TF32 GEMM: 128x128 tile, BK=32, 128 threads (4 warps), warp tile 64x64.
// A,B already tf32 in gmem; cp.async double-buffered smem; no cvt in loop.
// ---------------------------------------------------------------------------
struct GemmSmem {
    uint32_t As[2][128][36];
    uint32_t Bs[2][32][136];
};
#define SMEM_GEMM ((int)sizeof(GemmSmem))   // 71680 bytes

template<bool RELU, bool RES, bool OUTTF>
__device__ __forceinline__
void gemm_core(GemmSmem* sm,
               const uint32_t* __restrict__ A, const uint32_t* __restrict__ B,
               const float* __restrict__ bias, const float* __restrict__ res,
               void* __restrict__ Cv, int M, int N, int K, int bm, int bn)
{
    const int tid  = threadIdx.x;
    const int lane = tid & 31;
    const int wid  = tid >> 5;
    const int wm = (wid & 1) * 64;
    const int wn = (wid >> 1) * 64;
    const int grp = lane >> 2;
    const int tg  = lane & 3;

    float acc[4][8][4];
#pragma unroll
    for (int mt = 0; mt < 4; mt++)
#pragma unroll
        for (int nt = 0; nt < 8; nt++)
#pragma unroll
            for (int e = 0; e < 4; e++) acc[mt][nt][e] = 0.f;

    auto issue = [&](int s, int k0) {
#pragma unroll
        for (int p = 0; p < 8; p++) {
            int i  = tid + p*128;
            int r  = i >> 3;
            int c4 = (i & 7) * 4;
            cp_async16(&sm->As[s][r][c4], A + (size_t)(bm + r)*K + k0 + c4);
        }
#pragma unroll
        for (int p = 0; p < 8; p++) {
            int i  = tid + p*128;
            int r  = i >> 5;
            int c4 = (i & 31) * 4;
            cp_async16(&sm->Bs[s][r][c4], B + (size_t)(k0 + r)*N + bn + c4);
        }
        CP_COMMIT();
    };

    const int nIter = K >> 5;
    issue(0, 0);

    for (int it = 0; it < nIter; it++) {
        const int cur = it & 1;
        CP_WAIT0();
        __syncthreads();
        if (it + 1 < nIter) issue(cur ^ 1, (it + 1) << 5);

#pragma unroll
        for (int kk = 0; kk < 32; kk += 8) {
            uint32_t af[4][4], bf[8][2];
#pragma unroll
            for (int mt = 0; mt < 4; mt++) {
                int r = wm + mt*16 + grp;
                af[mt][0] = sm->As[cur][r    ][kk + tg    ];
                af[mt][1] = sm->As[cur][r + 8][kk + tg    ];
                af[mt][2] = sm->As[cur][r    ][kk + tg + 4];
                af[mt][3] = sm->As[cur][r + 8][kk + tg + 4];
            }
#pragma unroll
            for (int nt = 0; nt < 8; nt++) {
                int c = wn + nt*8 + grp;
                bf[nt][0] = sm->Bs[cur][kk + tg    ][c];
                bf[nt][1] = sm->Bs[cur][kk + tg + 4][c];
            }
#pragma unroll
            for (int mt = 0; mt < 4; mt++)
#pragma unroll
                for (int nt = 0; nt < 8; nt++)
                    mma_tf32(acc[mt][nt], af[mt], bf[nt]);
        }
    }

    // Epilogue
#pragma unroll
    for (int mt = 0; mt < 4; mt++) {
        int r0 = bm + wm + mt*16 + grp;
        int r1 = r0 + 8;
#pragma unroll
        for (int nt = 0; nt < 8; nt++) {
            int c = bn + wn + nt*8 + tg*2;
            float o0x = acc[mt][nt][0], o0y = acc[mt][nt][1];
            float o1x = acc[mt][nt][2], o1y = acc[mt][nt][3];
            if (bias) {
                float bv0 = bias[c], bv1 = bias[c+1];
                o0x += bv0; o0y += bv1; o1x += bv0; o1y += bv1;
            }
            if (RES) {
                float2 ra = *(const float2*)(res + (size_t)r0*N + c);
                float2 rb = *(const float2*)(res + (size_t)r1*N + c);
                o0x += ra.x; o0y += ra.y; o1x += rb.x; o1y += rb.y;
            }
            if (RELU) {
                o0x = fmaxf(o0x, 0.f); o0y = fmaxf(o0y, 0.f);
                o1x = fmaxf(o1x, 0.f); o1y = fmaxf(o1y, 0.f);
            }
            if (OUTTF) {
                uint32_t* C = (uint32_t*)Cv;
                uint2 w0 = {f2tf(o0x), f2tf(o0y)};
                uint2 w1 = {f2tf(o1x), f2tf(o1y)};
                *(uint2*)(C + (size_t)r0*N + c) = w0;
                *(uint2*)(C + (size_t)r1*N + c) = w1;
            } else {
                float* C = (float*)Cv;
                float2 w0 = {o0x, o0y};
                float2 w1 = {o1x, o1y};
                *(float2*)(C + (size_t)r0*N + c) = w0;
                *(float2*)(C + (size_t)r1*N + c) = w1;
            }
        }
    }
}

template<bool RELU, bool RES, bool OUTTF>
__global__ __launch_bounds__(128)
void tgemm(const uint32_t* __restrict__ A, const uint32_t* __restrict__ B,
           const float* __restrict__ bias, const float* __restrict__ res,
           void* __restrict__ C, int M, int N, int K)
{
    extern __shared__ GemmSmem smg[];
    gemm_core<RELU, RES, OUTTF>(smg, A, B, bias, res, C, M, N, K,
                                blockIdx.y * 128, blockIdx.x * 128);
}

// Fused QKV: grid.x = 9 (3 matrices x 3 col-tiles), grid.y = 64. tf32 out.
__global__ __launch_bounds__(128)
void qkv_gemm(const uint32_t* __restrict__ A,
              const uint32_t* __restrict__ Wq, const uint32_t* __restrict__ Wk,
              const uint32_t* __restrict__ Wv,
              uint32_t* __restrict__ Q, uint32_t* __restrict__ Ko, uint32_t* __restrict__ V)
{
    extern __shared__ GemmSmem smg[];
    int sel = blockIdx.x / 3;
    int bn  = (blockIdx.x % 3) * 128;
    const uint32_t* B = (sel == 0) ? Wq : (sel == 1) ? Wk : Wv;
    uint32_t*       C = (sel == 0) ? Q  : (sel == 1) ? Ko : V;
    gemm_core<false, false, true>(smg, A, B, nullptr, nullptr, C,
                                  MM, CC, CC, blockIdx.y * 128, bn);
}

// ---------------------------------------------------------------------------
// Tensor-core flash attention; q/k/v already tf32, att output tf32.
// ---------------------------------------------------------------------------
#define AKS 68
#define AVS 72
#define APS 36
#define ATT_SMEM ((TT*AKS + TT*AVS + 8*32*APS) * (int)sizeof(uint32_t))

__global__ __launch_bounds__(256, 1)
void attn_mma(const uint32_t* __restrict__ Q, const uint32_t* __restrict__ K,
              const uint32_t* __restrict__ V, uint32_t* __restrict__ O)
{
    extern __shared__ uint32_t sm[];
    uint32_t* Ks = sm;
    uint32_t* Vs = sm + TT*AKS;
    uint32_t* Pb = sm + TT*AKS + TT*AVS;

    const int bh = blockIdx.x;
    const int b  = bh / NH;
    const int h  = bh % NH;
    const float scale = 0.05103103630798288f;  // 1/sqrt(384)

    const int tid = threadIdx.x;
    const uint32_t* kbase = K + (size_t)b*TT*CC + h*HD;
    const uint32_t* vbase = V + (size_t)b*TT*CC + h*HD;

    for (int i = tid; i < TT*16; i += 256) {
        int t  = i >> 4;
        int d4 = (i & 15) * 4;
        *(uint4*)&Ks[t*AKS + d4] = *(const uint4*)(kbase + (size_t)t*CC + d4);
        *(uint4*)&Vs[t*AVS + d4] = *(const uint4*)(vbase + (size_t)t*CC + d4);
    }
    __syncthreads();

    const int lane = tid & 31;
    const int w    = tid >> 5;
    const int grp  = lane >> 2;
    const int tg   = lane & 3;
    const int q0   = w * 32;

    const uint32_t* qbase = Q + (size_t)b*TT*CC + h*HD;
    uint32_t qa[2][8][4];
#pragma unroll
    for (int mt = 0; mt < 2; mt++) {
        int ra = q0 + mt*16 + grp;
        int rb = ra + 8;
#pragma unroll
        for (int ks = 0; ks < 8; ks++) {
            int d = ks*8 + tg;
            qa[mt][ks][0] = qbase[(size_t)ra*CC + d    ];
            qa[mt][ks][1] = qbase[(size_t)rb*CC + d    ];
            qa[mt][ks][2] = qbase[(size_t)ra*CC + d + 4];
            qa[mt][ks][3] = qbase[(size_t)rb*CC + d + 4];
        }
    }

    float o[2][8][4];
#pragma unroll
    for (int mt = 0; mt < 2; mt++)
#pragma unroll
        for (int nt = 0; nt < 8; nt++)
#pragma unroll
            for (int e = 0; e < 4; e++) o[mt][nt][e] = 0.f;

    float mrow[2][2] = {{-1e30f,-1e30f},{-1e30f,-1e30f}};
    float lrow[2][2] = {{0.f,0.f},{0.f,0.f}};

    uint32_t* myP = Pb + w * 32 * APS;

    for (int j = 0; j <= w; j++) {
        const int kbeg = j * 32;
        float s[2][4][4];
#pragma unroll
        for (int mt = 0; mt < 2; mt++)
#pragma unroll
            for (int nt = 0; nt < 4; nt++)
#pragma unroll
                for (int e = 0; e < 4; e++) s[mt][nt][e] = 0.f;

#pragma unroll
        for (int ks = 0; ks < 8; ks++) {
            uint32_t bf[4][2];
#pragma unroll
            for (int nt = 0; nt < 4; nt++) {
                int key = kbeg + nt*8 + grp;
                int d   = ks*8 + tg;
                bf[nt][0] = Ks[key*AKS + d    ];
                bf[nt][1] = Ks[key*AKS + d + 4];
            }
#pragma unroll
            for (int mt = 0; mt < 2; mt++)
#pragma unroll
                for (int nt = 0; nt < 4; nt++)
                    mma_tf32(s[mt][nt], qa[mt][ks], bf[nt]);
        }

#pragma unroll
        for (int mt = 0; mt < 2; mt++) {
            int ra = q0 + mt*16 + grp;
            int rb = ra + 8;
            float rmax0 = -1e30f, rmax1 = -1e30f;
#pragma unroll
            for (int nt = 0; nt < 4; nt++) {
                int c0 = kbeg + nt*8 + 2*tg;
#pragma unroll
                for (int e = 0; e < 4; e++) {
                    float vv = s[mt][nt][e] * scale;
                    int col = c0 + (e & 1);
                    int row = (e < 2) ? ra : rb;
                    if (j == w && col > row) vv = -1e30f;
                    s[mt][nt][e] = vv;
                }
                rmax0 = fmaxf(rmax0, fmaxf(s[mt][nt][0], s[mt][nt][1]));
                rmax1 = fmaxf(rmax1, fmaxf(s[mt][nt][2], s[mt][nt][3]));
            }
            rmax0 = fmaxf(rmax0, __shfl_xor_sync(0xFFFFFFFFu, rmax0, 1));
            rmax0 = fmaxf(rmax0, __shfl_xor_sync(0xFFFFFFFFu, rmax0, 2));
            rmax1 = fmaxf(rmax1, __shfl_xor_sync(0xFFFFFFFFu, rmax1, 1));
            rmax1 = fmaxf(rmax1, __shfl_xor_sync(0xFFFFFFFFu, rmax1, 2));

            float mn0 = fmaxf(mrow[mt][0], rmax0);
            float mn1 = fmaxf(mrow[mt][1], rmax1);
            float cr0 = __expf(mrow[mt][0] - mn0);
            float cr1 = __expf(mrow[mt][1] - mn1);
            mrow[mt][0] = mn0; mrow[mt][1] = mn1;

            float rs0 = 0.f, rs1 = 0.f;
#pragma unroll
            for (int nt = 0; nt < 4; nt++) {
                float p0 = __expf(s[mt][nt][0] - mn0);
                float p1 = __expf(s[mt][nt][1] - mn0);
                float p2 = __expf(s[mt][nt][2] - mn1);
                float p3 = __expf(s[mt][nt][3] - mn1);
                rs0 += p0 + p1; rs1 += p2 + p3;
                int cb = nt*8 + 2*tg;
                myP[(mt*16 + grp    )*APS + cb    ] = f2tf(p0);
                myP[(mt*16 + grp    )*APS + cb + 1] = f2tf(p1);
                myP[(mt*16 + grp + 8)*APS + cb    ] = f2tf(p2);
                myP[(mt*16 + grp + 8)*APS + cb + 1] = f2tf(p3);
            }
            rs0 += __shfl_xor_sync(0xFFFFFFFFu, rs0, 1);
            rs0 += __shfl_xor_sync(0xFFFFFFFFu, rs0, 2);
            rs1 += __shfl_xor_sync(0xFFFFFFFFu, rs1, 1);
            rs1 += __shfl_xor_sync(0xFFFFFFFFu, rs1, 2);
            lrow[mt][0] = lrow[mt][0]*cr0 + rs0;
            lrow[mt][1] = lrow[mt][1]*cr1 + rs1;
#pragma unroll
            for (int nt = 0; nt < 8; nt++) {
                o[mt][nt][0] *= cr0; o[mt][nt][1] *= cr0;
                o[mt][nt][2] *= cr1; o[mt][nt][3] *= cr1;
            }
        }
        __syncwarp();

#pragma unroll
        for (int ks2 = 0; ks2 < 4; ks2++) {
            uint32_t vb[8][2];
#pragma unroll
            for (int nt = 0; nt < 8; nt++) {
                int key = kbeg + ks2*8 + tg;
                int d   = nt*8 + grp;
                vb[nt][0] = Vs[ key     *AVS + d];
                vb[nt][1] = Vs[(key + 4)*AVS + d];
            }
#pragma unroll
            for (int mt = 0; mt < 2; mt++) {
                uint32_t pa[4];
                pa[0] = myP[(mt*16 + grp    )*APS + ks2*8 + tg    ];
                pa[1] = myP[(mt*16 + grp + 8)*APS + ks2*8 + tg    ];
                pa[2] = myP[(mt*16 + grp    )*APS + ks2*8 + tg + 4];
                pa[3] = myP[(mt*16 + grp + 8)*APS + ks2*8 + tg + 4];
#pragma unroll
                for (int nt = 0; nt < 8; nt++)
                    mma_tf32(o[mt][nt], pa, vb[nt]);
            }
        }
        __syncwarp();
    }

    uint32_t* obase = O + (size_t)b*TT*CC + h*HD;
#pragma unroll
    for (int mt = 0; mt < 2; mt++) {
        int ra = q0 + mt*16 + grp;
        int rb = ra + 8;
        float inv0 = 1.f / lrow[mt][0];
        float inv1 = 1.f / lrow[mt][1];
#pragma unroll
        for (int nt = 0; nt < 8; nt++) {
            int d = nt*8 + 2*tg;
            uint2 w0 = {f2tf(o[mt][nt][0]*inv0), f2tf(o[mt][nt][1]*inv0)};
            uint2 w1 = {f2tf(o[mt][nt][2]*inv1), f2tf(o[mt][nt][3]*inv1)};
            *(uint2*)(obase + (size_t)ra*CC + d) = w0;
            *(uint2*)(obase + (size_t)rb*CC + d) = w1;
        }
    }
}

// ---------------------------------------------------------------------------
// Host
// ---------------------------------------------------------------------------
static void cvt(const float* src, uint32_t* dst, int n) {
    int n4 = n / 4;
    cvt_kernel<<<(n4 + 255)/256, 256>>>(src, dst, n4);
}

extern "C" void kernel_launch(void* const* d_in, const int* in_sizes, int n_in,
                              void* d_out, int out_size)
{
    (void)in_sizes; (void)n_in; (void)out_size;

    const int*   idx     = (const int*)  d_in[0];
    const float* tok_emb = (const float*)d_in[1];
    const float* pos_emb = (const float*)d_in[2];
    const float* ln1_g   = (const float*)d_in[3];
    const float* ln1_b   = (const float*)d_in[4];
    const float* wq      = (const float*)d_in[5];
    const float* wk      = (const float*)d_in[6];
    const float* wv      = (const float*)d_in[7];
    const float* wo      = (const float*)d_in[8];
    const float* wo_b    = (const float*)d_in[9];
    const float* ln2_g   = (const float*)d_in[10];
    const float* ln2_b   = (const float*)d_in[11];
    const float* w1      = (const float*)d_in[12];
    const float* b1      = (const float*)d_in[13];
    const float* w2      = (const float*)d_in[14];
    const float* b2      = (const float*)d_in[15];
    const float* lnf_g   = (const float*)d_in[16];
    const float* lnf_b   = (const float*)d_in[17];
    const float* lm_w    = (const float*)d_in[18];
    const float* lm_b    = (const float*)d_in[19];
    float* out = (float*)d_out;

    float *x;
    uint32_t *h, *q, *k, *v, *att, *u, *wt;
    cudaGetSymbolAddress((void**)&x,   g_x);
    cudaGetSymbolAddress((void**)&h,   g_h);
    cudaGetSymbolAddress((void**)&q,   g_q);
    cudaGetSymbolAddress((void**)&k,   g_k);
    cudaGetSymbolAddress((void**)&v,   g_v);
    cudaGetSymbolAddress((void**)&att, g_att);
    cudaGetSymbolAddress((void**)&u,   g_u);
    cudaGetSymbolAddress((void**)&wt,  g_wt);

    cudaFuncSetAttribute(attn_mma, cudaFuncAttributeMaxDynamicSharedMemorySize, ATT_SMEM);
    cudaFuncSetAttribute(tgemm<false,false,false>, cudaFuncAttributeMaxDynamicSharedMemorySize, SMEM_GEMM);
    cudaFuncSetAttribute(tgemm<false,true ,false>, cudaFuncAttributeMaxDynamicSharedMemorySize, SMEM_GEMM);
    cudaFuncSetAttribute(tgemm<true ,false,true >, cudaFuncAttributeMaxDynamicSharedMemorySize, SMEM_GEMM);
    cudaFuncSetAttribute(qkv_gemm,                 cudaFuncAttributeMaxDynamicSharedMemorySize, SMEM_GEMM);

    // Pre-convert all weights to tf32
    cvt(wq,   wt + OFF_WQ, LL*CC*CC);
    cvt(wk,   wt + OFF_WK, LL*CC*CC);
    cvt(wv,   wt + OFF_WV, LL*CC*CC);
    cvt(wo,   wt + OFF_WO, LL*CC*CC);
    cvt(w1,   wt + OFF_W1, LL*CC*FF);
    cvt(w2,   wt + OFF_W2, LL*FF*CC);
    cvt(lm_w, wt + OFF_LM, CC*VV);

    {
        int total = MM * (CC/4);
        embed_kernel<<<(total + 255)/256, 256>>>(idx, tok_emb, pos_emb, x);
    }

    for (int L = 0; L < LL; L++) {
        const float* g1  = ln1_g + (size_t)L*CC;
        const float* bg1 = ln1_b + (size_t)L*CC;
        const uint32_t* Wq = wt + OFF_WQ + (size_t)L*CC*CC;
        const uint32_t* Wk = wt + OFF_WK + (size_t)L*CC*CC;
        const uint32_t* Wv = wt + OFF_WV + (size_t)L*CC*CC;
        const uint32_t* Wo = wt + OFF_WO + (size_t)L*CC*CC;
        const float* Wob = wo_b + (size_t)L*CC;
        const float* g2  = ln2_g + (size_t)L*CC;
        const float* bg2 = ln2_b + (size_t)L*CC;
        const uint32_t* W1 = wt + OFF_W1 + (size_t)L*CC*FF;
        const float* B1  = b1 + (size_t)L*FF;
        const uint32_t* W2 = wt + OFF_W2 + (size_t)L*FF*CC;
        const float* B2  = b2 + (size_t)L*CC;

        ln_kernel<<<MM/8, 256>>>(x, g1, bg1, h);
        qkv_gemm<<<dim3(9, 64), 128, SMEM_GEMM>>>(h, Wq, Wk, Wv, q, k, v);
        attn_mma<<<BB*NH, 256, ATT_SMEM>>>(q, k, v, att);
        // x += att @ Wo + wo_b
        tgemm<false,true,false><<<dim3(CC/128, MM/128), 128, SMEM_GEMM>>>(
            att, Wo, Wob, x, x, MM, CC, CC);
        ln_kernel<<<MM/8, 256>>>(x, g2, bg2, h);
        // u = relu(h @ W1 + b1), tf32 out
        tgemm<true,false,true><<<dim3(FF/128, MM/128), 128, SMEM_GEMM>>>(
            h, W1, B1, nullptr, u, MM, FF, CC);
        // x += u @ W2 + b2
        tgemm<false,true,false><<<dim3(CC/128, MM/128), 128, SMEM_GEMM>>>(
            u, W2, B2, x, x, MM, CC, FF);
    }

    ln_kernel<<<MM/8, 256>>>(x, lnf_g, lnf_b, h);
    // logits = h @ lm_w + lm_b
    tgemm<false,false,false><<<dim3(VV/128, MM/128), 128, SMEM_GEMM>>>(
        h, wt + OFF_LM, lm_b, nullptr, out, MM, VV, CC);
}